// round 12
// baseline (speedup 1.0000x reference)
#include <cuda_runtime.h>

// Problem constants (fixed by the dataset)
#define BATCH  4096
#define TT     1000
#define HID    32
#define HH     15    // padded to 16
#define OUTD   8
#define INITD  16

#define NTHR   128                    // threads per block
#define EPB    (NTHR / 8)             // 16 elements per block (8 threads/element)
#define NBLK   (BATCH / EPB)          // 256 blocks -> 1024 warps ~ 2/SMSP

typedef unsigned long long u64;

__device__ __forceinline__ u64 pack2(float x, float y) {
    u64 r; asm("mov.b64 %0, {%1,%2};" : "=l"(r) : "f"(x), "f"(y)); return r;
}
__device__ __forceinline__ float2 unpack2(u64 v) {
    float2 p; asm("mov.b64 {%0,%1}, %2;" : "=f"(p.x), "=f"(p.y) : "l"(v)); return p;
}
// Packed f32x2 FMA / ADD (sm_100+; ptxas will not auto-fuse these)
__device__ __forceinline__ u64 fma2(u64 a, u64 b, u64 c) {
    u64 d; asm("fma.rn.f32x2 %0, %1, %2, %3;" : "=l"(d) : "l"(a), "l"(b), "l"(c)); return d;
}
__device__ __forceinline__ u64 add2(u64 a, u64 b) {
    u64 d; asm("add.rn.f32x2 %0, %1, %2;" : "=l"(d) : "l"(a), "l"(b)); return d;
}

__device__ __forceinline__ float ftanh(float x) {
    x = fminf(fmaxf(x, -15.f), 15.f);
    float e = __expf(2.f * x);
    return __fdividef(e - 1.f, e + 1.f);
}

// dot over 32 inputs: v = 16 packed k-pairs, weights = contiguous 32-float row
__device__ __forceinline__ float dot32p(const float* __restrict__ row,
                                        const u64 (&v)[16], float bias) {
    u64 acc0 = pack2(bias, 0.f);
    u64 acc1 = pack2(0.f, 0.f);
#pragma unroll
    for (int kk = 0; kk < 8; kk++) {
        ulonglong2 w = *(const ulonglong2*)(row + 4 * kk);  // 4 floats = 2 k-pairs
        acc0 = fma2(v[2 * kk + 0], w.x, acc0);
        acc1 = fma2(v[2 * kk + 1], w.y, acc1);
    }
    float2 s = unpack2(add2(acc0, acc1));
    return s.x + s.y;
}

// dot over 16 inputs: v = 8 packed k-pairs, weights = contiguous 16-float row
__device__ __forceinline__ float dot16p(const float* __restrict__ row,
                                        const u64 (&v)[8], float bias) {
    u64 acc0 = pack2(bias, 0.f);
    u64 acc1 = pack2(0.f, 0.f);
#pragma unroll
    for (int kk = 0; kk < 4; kk++) {
        ulonglong2 w = *(const ulonglong2*)(row + 4 * kk);
        acc0 = fma2(v[2 * kk + 0], w.x, acc0);
        acc1 = fma2(v[2 * kk + 1], w.y, acc1);
    }
    float2 s = unpack2(add2(acc0, acc1));
    return s.x + s.y;
}

__global__ void __launch_bounds__(NTHR) node_kernel(
    const float* __restrict__ times, const float* __restrict__ initial,
    const float* __restrict__ Wi,  const float* __restrict__ bi,
    const float* __restrict__ Wf0, const float* __restrict__ bf0,
    const float* __restrict__ Wf1, const float* __restrict__ bf1,
    const float* __restrict__ Wf2, const float* __restrict__ bf2,
    const float* __restrict__ Wf3, const float* __restrict__ bf3,
    const float* __restrict__ Wl,  const float* __restrict__ bl,
    float* __restrict__ out)
{
    // Transposed weights, even/odd output rows in separate arrays.
    // Row strides (in floats): 36 (144B) and 20 (80B) ->
    //   lanes r=0..7 read base + r*stride: offsets mod 128B are all distinct
    //   (144: {0,16,..,112}; 80: {0,80,32,112,64,16,96,48}) -> conflict-free LDS.128.
    __shared__ __align__(16) float sW0e[8][36],  sW0o[8][36];   // rows 2r / 2r+1, k<32
    __shared__ __align__(16) float sW1e[8][20],  sW1o[8][20];   // k<16 (15 + pad)
    __shared__ __align__(16) float sW2e[8][20],  sW2o[8][20];
    __shared__ __align__(16) float sW3e[16][20], sW3o[16][20];  // rows 2c / 2c+1, c<16
    __shared__ __align__(16) float sWl[8][36];                  // [o][k], k<32
    __shared__ __align__(16) float sWi[INITD][HID];
    __shared__ float sB0[16], sB1[16], sB2[16], sB3[HID], sBl[OUTD];
    __shared__ float sDt[TT - 1];

    const int tid = threadIdx.x;

    // ---- zero the padded arrays that get loaded (pads must read 0) ----
    for (int i = tid; i < 8 * 36; i += NTHR) { (&sW0e[0][0])[i] = 0.f; (&sW0o[0][0])[i] = 0.f; }
    for (int i = tid; i < 8 * 20; i += NTHR) {
        (&sW1e[0][0])[i] = 0.f; (&sW1o[0][0])[i] = 0.f;
        (&sW2e[0][0])[i] = 0.f; (&sW2o[0][0])[i] = 0.f;
    }
    for (int i = tid; i < 16 * 20; i += NTHR) { (&sW3e[0][0])[i] = 0.f; (&sW3o[0][0])[i] = 0.f; }
    __syncthreads();

    // ---- fill transposed weights ----
    for (int i = tid; i < HID * HH; i += NTHR) {          // Wf0 [32][15]
        int k = i / HH, j = i % HH; float w = Wf0[i];
        if (j & 1) sW0o[j >> 1][k] = w; else sW0e[j >> 1][k] = w;
    }
    for (int i = tid; i < HH * HH; i += NTHR) {           // Wf1/Wf2 [15][15]
        int k = i / HH, j = i % HH;
        if (j & 1) { sW1o[j >> 1][k] = Wf1[i]; sW2o[j >> 1][k] = Wf2[i]; }
        else       { sW1e[j >> 1][k] = Wf1[i]; sW2e[j >> 1][k] = Wf2[i]; }
    }
    for (int i = tid; i < HH * HID; i += NTHR) {          // Wf3 [15][32]
        int k = i / HID, c = i % HID; float w = Wf3[i];
        if (c & 1) sW3o[c >> 1][k] = w; else sW3e[c >> 1][k] = w;
    }
    for (int i = tid; i < HID * OUTD; i += NTHR) {        // Wl [32][8]
        int k = i / OUTD, o = i % OUTD; sWl[o][k] = Wl[i];
    }
    for (int i = tid; i < INITD * HID; i += NTHR) (&sWi[0][0])[i] = Wi[i];
    if (tid < 16) {
        sB0[tid] = (tid < HH) ? bf0[tid] : 0.f;
        sB1[tid] = (tid < HH) ? bf1[tid] : 0.f;
        sB2[tid] = (tid < HH) ? bf2[tid] : 0.f;
    }
    if (tid < HID)  sB3[tid] = bf3[tid];
    if (tid < OUTD) sBl[tid] = bl[tid];
    for (int t = tid; t < TT - 1; t += NTHR) sDt[t] = times[t + 1] - times[t];
    __syncthreads();

    // ---- mapping: 8 consecutive lanes = one batch element ----
    const int e = blockIdx.x * EPB + (tid >> 3);
    const int r = tid & 7;                     // role 0..7
    const unsigned FULL = 0xffffffffu;

    // ---- h0 = initial @ Wi + bi (replicated across the 8 roles), kept packed ----
    u64 hp[16];
    {
        float x[INITD];
#pragma unroll
        for (int k = 0; k < INITD; k++) x[k] = initial[e * INITD + k];
#pragma unroll
        for (int j = 0; j < 16; j++) {
            float a = bi[2 * j], b = bi[2 * j + 1];
#pragma unroll
            for (int k = 0; k < INITD; k++) {
                a = fmaf(x[k], sWi[k][2 * j],     a);
                b = fmaf(x[k], sWi[k][2 * j + 1], b);
            }
            hp[j] = pack2(a, b);
        }
    }

    float* __restrict__ oute = out + (size_t)e * TT * OUTD;
    const float b0e = sB0[2 * r], b0o = sB0[2 * r + 1];
    const float b1e = sB1[2 * r], b1o = sB1[2 * r + 1];
    const float b2e = sB2[2 * r], b2o = sB2[2 * r + 1];
    const float b3a = sB3[2 * r],      b3b = sB3[2 * r + 1];
    const float b3c = sB3[2 * r + 16], b3d = sB3[2 * r + 17];
    const float blr = sBl[r];

    // projection: role r writes output column o = r
    oute[r] = dot32p(&sWl[r][0], hp, blr);

    for (int t = 0; t < TT - 1; t++) {
        const float dt = sDt[t];
        const u64 dt2 = pack2(dt, dt);

        // ---- layer 0: 32 -> 16, role r owns rows 2r and 2r+1 ----
        float a0 = ftanh(dot32p(&sW0e[r][0], hp, b0e));
        float a1 = ftanh(dot32p(&sW0o[r][0], hp, b0o));
        u64 zp[8];
        u64 pl = pack2(a0, a1);                     // {z_2r, z_2r+1}
#pragma unroll
        for (int j = 0; j < 8; j++) zp[j] = __shfl_sync(FULL, pl, j, 8);

        // ---- layer 1: 16 -> 16 ----
        a0 = ftanh(dot16p(&sW1e[r][0], zp, b1e));
        a1 = ftanh(dot16p(&sW1o[r][0], zp, b1o));
        pl = pack2(a0, a1);
#pragma unroll
        for (int j = 0; j < 8; j++) zp[j] = __shfl_sync(FULL, pl, j, 8);

        // ---- layer 2: 16 -> 16 ----
        a0 = ftanh(dot16p(&sW2e[r][0], zp, b2e));
        a1 = ftanh(dot16p(&sW2o[r][0], zp, b2o));
        pl = pack2(a0, a1);
#pragma unroll
        for (int j = 0; j < 8; j++) zp[j] = __shfl_sync(FULL, pl, j, 8);

        // ---- layer 3: 16 -> 32, role r owns rows 2r,2r+1,2r+16,2r+17 ----
        float f0 = dot16p(&sW3e[r][0],     zp, b3a);
        float f1 = dot16p(&sW3o[r][0],     zp, b3b);
        float f2 = dot16p(&sW3e[r + 8][0], zp, b3c);
        float f3 = dot16p(&sW3o[r + 8][0], zp, b3d);
        const u64 fp0 = pack2(f0, f1);              // {f_2r,    f_2r+1}
        const u64 fp1 = pack2(f2, f3);              // {f_2r+16, f_2r+17}

        // ---- h += dt * f (packed pairwise all-gather) ----
#pragma unroll
        for (int j = 0; j < 8; j++) {
            hp[j]     = fma2(__shfl_sync(FULL, fp0, j, 8), dt2, hp[j]);
            hp[j + 8] = fma2(__shfl_sync(FULL, fp1, j, 8), dt2, hp[j + 8]);
        }

        // ---- projection at t+1 ----
        oute[(size_t)(t + 1) * OUTD + r] = dot32p(&sWl[r][0], hp, blr);
    }
}

extern "C" void kernel_launch(void* const* d_in, const int* in_sizes, int n_in,
                              void* d_out, int out_size) {
    const float* times   = (const float*)d_in[0];
    const float* initial = (const float*)d_in[1];
    const float* Wi  = (const float*)d_in[2];
    const float* bi  = (const float*)d_in[3];
    const float* Wf0 = (const float*)d_in[4];
    const float* bf0 = (const float*)d_in[5];
    const float* Wf1 = (const float*)d_in[6];
    const float* bf1 = (const float*)d_in[7];
    const float* Wf2 = (const float*)d_in[8];
    const float* bf2 = (const float*)d_in[9];
    const float* Wf3 = (const float*)d_in[10];
    const float* bf3 = (const float*)d_in[11];
    const float* Wl  = (const float*)d_in[12];
    const float* bl  = (const float*)d_in[13];
    float* out = (float*)d_out;

    node_kernel<<<NBLK, NTHR>>>(times, initial, Wi, bi,
                                Wf0, bf0, Wf1, bf1, Wf2, bf2, Wf3, bf3,
                                Wl, bl, out);
}

// round 13
// speedup vs baseline: 1.0007x; 1.0007x over previous
#include <cuda_runtime.h>

// Problem constants (fixed by the dataset)
#define BATCH  4096
#define TT     1000
#define HID    32
#define HH     15    // padded to 16
#define OUTD   8
#define INITD  16

#define NTHR   128                    // threads per block
#define EPB    (NTHR / 8)             // 16 elements per block (8 threads/element)
#define NBLK   (BATCH / EPB)          // 256 blocks -> 1024 warps ~ 2/SMSP

typedef unsigned long long u64;

__device__ __forceinline__ u64 pack2(float x, float y) {
    u64 r; asm("mov.b64 %0, {%1,%2};" : "=l"(r) : "f"(x), "f"(y)); return r;
}
__device__ __forceinline__ float2 unpack2(u64 v) {
    float2 p; asm("mov.b64 {%0,%1}, %2;" : "=f"(p.x), "=f"(p.y) : "l"(v)); return p;
}
// Packed f32x2 FMA / ADD (sm_100+; ptxas will not auto-fuse these)
__device__ __forceinline__ u64 fma2(u64 a, u64 b, u64 c) {
    u64 d; asm("fma.rn.f32x2 %0, %1, %2, %3;" : "=l"(d) : "l"(a), "l"(b), "l"(c)); return d;
}
__device__ __forceinline__ u64 add2(u64 a, u64 b) {
    u64 d; asm("add.rn.f32x2 %0, %1, %2;" : "=l"(d) : "l"(a), "l"(b)); return d;
}

__device__ __forceinline__ float ftanh(float x) {
    x = fminf(fmaxf(x, -15.f), 15.f);
    float e = __expf(2.f * x);
    return __fdividef(e - 1.f, e + 1.f);
}

// dot over 32 inputs: v = 16 packed k-pairs, weights = contiguous 32-float row
__device__ __forceinline__ float dot32p(const float* __restrict__ row,
                                        const u64 (&v)[16], float bias) {
    u64 acc0 = pack2(bias, 0.f);
    u64 acc1 = pack2(0.f, 0.f);
#pragma unroll
    for (int kk = 0; kk < 8; kk++) {
        ulonglong2 w = *(const ulonglong2*)(row + 4 * kk);  // 4 floats = 2 k-pairs
        acc0 = fma2(v[2 * kk + 0], w.x, acc0);
        acc1 = fma2(v[2 * kk + 1], w.y, acc1);
    }
    float2 s = unpack2(add2(acc0, acc1));
    return s.x + s.y;
}

// dot over 16 inputs: v = 8 packed k-pairs, weights = contiguous 16-float row
__device__ __forceinline__ float dot16p(const float* __restrict__ row,
                                        const u64 (&v)[8], float bias) {
    u64 acc0 = pack2(bias, 0.f);
    u64 acc1 = pack2(0.f, 0.f);
#pragma unroll
    for (int kk = 0; kk < 4; kk++) {
        ulonglong2 w = *(const ulonglong2*)(row + 4 * kk);
        acc0 = fma2(v[2 * kk + 0], w.x, acc0);
        acc1 = fma2(v[2 * kk + 1], w.y, acc1);
    }
    float2 s = unpack2(add2(acc0, acc1));
    return s.x + s.y;
}

__global__ void __launch_bounds__(NTHR) node_kernel(
    const float* __restrict__ times, const float* __restrict__ initial,
    const float* __restrict__ Wi,  const float* __restrict__ bi,
    const float* __restrict__ Wf0, const float* __restrict__ bf0,
    const float* __restrict__ Wf1, const float* __restrict__ bf1,
    const float* __restrict__ Wf2, const float* __restrict__ bf2,
    const float* __restrict__ Wf3, const float* __restrict__ bf3,
    const float* __restrict__ Wl,  const float* __restrict__ bl,
    float* __restrict__ out)
{
    // Transposed weights, even/odd output rows in separate arrays.
    // Row strides (in floats): 36 (144B) and 20 (80B) ->
    //   lanes r=0..7 read base + r*stride: offsets mod 128B are all distinct
    //   (144: {0,16,..,112}; 80: {0,80,32,112,64,16,96,48}) -> conflict-free LDS.128.
    __shared__ __align__(16) float sW0e[8][36],  sW0o[8][36];   // rows 2r / 2r+1, k<32
    __shared__ __align__(16) float sW1e[8][20],  sW1o[8][20];   // k<16 (15 + pad)
    __shared__ __align__(16) float sW2e[8][20],  sW2o[8][20];
    __shared__ __align__(16) float sW3e[16][20], sW3o[16][20];  // rows 2c / 2c+1, c<16
    __shared__ __align__(16) float sWl[8][36];                  // [o][k], k<32
    __shared__ __align__(16) float sWi[INITD][HID];
    __shared__ float sB0[16], sB1[16], sB2[16], sB3[HID], sBl[OUTD];
    __shared__ float sDt[TT - 1];

    const int tid = threadIdx.x;

    // ---- zero the padded arrays that get loaded (pads must read 0) ----
    for (int i = tid; i < 8 * 36; i += NTHR) { (&sW0e[0][0])[i] = 0.f; (&sW0o[0][0])[i] = 0.f; }
    for (int i = tid; i < 8 * 20; i += NTHR) {
        (&sW1e[0][0])[i] = 0.f; (&sW1o[0][0])[i] = 0.f;
        (&sW2e[0][0])[i] = 0.f; (&sW2o[0][0])[i] = 0.f;
    }
    for (int i = tid; i < 16 * 20; i += NTHR) { (&sW3e[0][0])[i] = 0.f; (&sW3o[0][0])[i] = 0.f; }
    __syncthreads();

    // ---- fill transposed weights ----
    for (int i = tid; i < HID * HH; i += NTHR) {          // Wf0 [32][15]
        int k = i / HH, j = i % HH; float w = Wf0[i];
        if (j & 1) sW0o[j >> 1][k] = w; else sW0e[j >> 1][k] = w;
    }
    for (int i = tid; i < HH * HH; i += NTHR) {           // Wf1/Wf2 [15][15]
        int k = i / HH, j = i % HH;
        if (j & 1) { sW1o[j >> 1][k] = Wf1[i]; sW2o[j >> 1][k] = Wf2[i]; }
        else       { sW1e[j >> 1][k] = Wf1[i]; sW2e[j >> 1][k] = Wf2[i]; }
    }
    for (int i = tid; i < HH * HID; i += NTHR) {          // Wf3 [15][32]
        int k = i / HID, c = i % HID; float w = Wf3[i];
        if (c & 1) sW3o[c >> 1][k] = w; else sW3e[c >> 1][k] = w;
    }
    for (int i = tid; i < HID * OUTD; i += NTHR) {        // Wl [32][8]
        int k = i / OUTD, o = i % OUTD; sWl[o][k] = Wl[i];
    }
    for (int i = tid; i < INITD * HID; i += NTHR) (&sWi[0][0])[i] = Wi[i];
    if (tid < 16) {
        sB0[tid] = (tid < HH) ? bf0[tid] : 0.f;
        sB1[tid] = (tid < HH) ? bf1[tid] : 0.f;
        sB2[tid] = (tid < HH) ? bf2[tid] : 0.f;
    }
    if (tid < HID)  sB3[tid] = bf3[tid];
    if (tid < OUTD) sBl[tid] = bl[tid];
    for (int t = tid; t < TT - 1; t += NTHR) sDt[t] = times[t + 1] - times[t];
    __syncthreads();

    // ---- mapping: 8 consecutive lanes = one batch element ----
    const int e = blockIdx.x * EPB + (tid >> 3);
    const int r = tid & 7;                     // role 0..7
    const unsigned FULL = 0xffffffffu;

    // ---- h0 = initial @ Wi + bi (replicated across the 8 roles), kept packed ----
    u64 hp[16];
    {
        float x[INITD];
#pragma unroll
        for (int k = 0; k < INITD; k++) x[k] = initial[e * INITD + k];
#pragma unroll
        for (int j = 0; j < 16; j++) {
            float a = bi[2 * j], b = bi[2 * j + 1];
#pragma unroll
            for (int k = 0; k < INITD; k++) {
                a = fmaf(x[k], sWi[k][2 * j],     a);
                b = fmaf(x[k], sWi[k][2 * j + 1], b);
            }
            hp[j] = pack2(a, b);
        }
    }

    float* __restrict__ oute = out + (size_t)e * TT * OUTD;
    const float b0e = sB0[2 * r], b0o = sB0[2 * r + 1];
    const float b1e = sB1[2 * r], b1o = sB1[2 * r + 1];
    const float b2e = sB2[2 * r], b2o = sB2[2 * r + 1];
    const float b3a = sB3[2 * r],      b3b = sB3[2 * r + 1];
    const float b3c = sB3[2 * r + 16], b3d = sB3[2 * r + 17];
    const float blr = sBl[r];

    // projection: role r writes output column o = r
    oute[r] = dot32p(&sWl[r][0], hp, blr);

    for (int t = 0; t < TT - 1; t++) {
        const float dt = sDt[t];
        const u64 dt2 = pack2(dt, dt);

        // ---- layer 0: 32 -> 16, role r owns rows 2r and 2r+1 ----
        float a0 = ftanh(dot32p(&sW0e[r][0], hp, b0e));
        float a1 = ftanh(dot32p(&sW0o[r][0], hp, b0o));
        u64 zp[8];
        u64 pl = pack2(a0, a1);                     // {z_2r, z_2r+1}
#pragma unroll
        for (int j = 0; j < 8; j++) zp[j] = __shfl_sync(FULL, pl, j, 8);

        // ---- layer 1: 16 -> 16 ----
        a0 = ftanh(dot16p(&sW1e[r][0], zp, b1e));
        a1 = ftanh(dot16p(&sW1o[r][0], zp, b1o));
        pl = pack2(a0, a1);
#pragma unroll
        for (int j = 0; j < 8; j++) zp[j] = __shfl_sync(FULL, pl, j, 8);

        // ---- layer 2: 16 -> 16 ----
        a0 = ftanh(dot16p(&sW2e[r][0], zp, b2e));
        a1 = ftanh(dot16p(&sW2o[r][0], zp, b2o));
        pl = pack2(a0, a1);
#pragma unroll
        for (int j = 0; j < 8; j++) zp[j] = __shfl_sync(FULL, pl, j, 8);

        // ---- layer 3: 16 -> 32, role r owns rows 2r,2r+1,2r+16,2r+17 ----
        float f0 = dot16p(&sW3e[r][0],     zp, b3a);
        float f1 = dot16p(&sW3o[r][0],     zp, b3b);
        float f2 = dot16p(&sW3e[r + 8][0], zp, b3c);
        float f3 = dot16p(&sW3o[r + 8][0], zp, b3d);
        const u64 fp0 = pack2(f0, f1);              // {f_2r,    f_2r+1}
        const u64 fp1 = pack2(f2, f3);              // {f_2r+16, f_2r+17}

        // ---- h += dt * f (packed pairwise all-gather) ----
#pragma unroll
        for (int j = 0; j < 8; j++) {
            hp[j]     = fma2(__shfl_sync(FULL, fp0, j, 8), dt2, hp[j]);
            hp[j + 8] = fma2(__shfl_sync(FULL, fp1, j, 8), dt2, hp[j + 8]);
        }

        // ---- projection at t+1 ----
        oute[(size_t)(t + 1) * OUTD + r] = dot32p(&sWl[r][0], hp, blr);
    }
}

extern "C" void kernel_launch(void* const* d_in, const int* in_sizes, int n_in,
                              void* d_out, int out_size) {
    const float* times   = (const float*)d_in[0];
    const float* initial = (const float*)d_in[1];
    const float* Wi  = (const float*)d_in[2];
    const float* bi  = (const float*)d_in[3];
    const float* Wf0 = (const float*)d_in[4];
    const float* bf0 = (const float*)d_in[5];
    const float* Wf1 = (const float*)d_in[6];
    const float* bf1 = (const float*)d_in[7];
    const float* Wf2 = (const float*)d_in[8];
    const float* bf2 = (const float*)d_in[9];
    const float* Wf3 = (const float*)d_in[10];
    const float* bf3 = (const float*)d_in[11];
    const float* Wl  = (const float*)d_in[12];
    const float* bl  = (const float*)d_in[13];
    float* out = (float*)d_out;

    node_kernel<<<NBLK, NTHR>>>(times, initial, Wi, bi,
                                Wf0, bf0, Wf1, bf1, Wf2, bf2, Wf3, bf3,
                                Wl, bl, out);
}

// round 14
// speedup vs baseline: 3.2196x; 3.2174x over previous
#include <cuda_runtime.h>

// Problem constants (fixed by the dataset)
#define BATCH  4096
#define TT     1000
#define HID    32
#define HH     15    // padded to 16
#define OUTD   8
#define INITD  16

#define NTHR   128                    // threads per block
#define EPB    (NTHR / 8)             // 16 elements per block (8 threads/element)
#define NBLK   (BATCH / EPB)          // 256 blocks

typedef unsigned long long u64;

__device__ __forceinline__ u64 pack2(float x, float y) {
    u64 r; asm("mov.b64 %0, {%1,%2};" : "=l"(r) : "f"(x), "f"(y)); return r;
}
__device__ __forceinline__ float2 unpack2(u64 v) {
    float2 p; asm("mov.b64 {%0,%1}, %2;" : "=f"(p.x), "=f"(p.y) : "l"(v)); return p;
}
// Packed f32x2 FMA / ADD (sm_100+; ptxas will not auto-fuse these)
__device__ __forceinline__ u64 fma2(u64 a, u64 b, u64 c) {
    u64 d; asm("fma.rn.f32x2 %0, %1, %2, %3;" : "=l"(d) : "l"(a), "l"(b), "l"(c)); return d;
}
__device__ __forceinline__ u64 add2(u64 a, u64 b) {
    u64 d; asm("add.rn.f32x2 %0, %1, %2;" : "=l"(d) : "l"(a), "l"(b)); return d;
}

// tanh(x) = 1 - 2/(e^{2x}+1).  No clamp needed: e->inf gives 1, e->0 gives -1.
__device__ __forceinline__ float ftanh(float x) {
    float e = __expf(2.f * x);
    return 1.f - __fdividef(2.f, e + 1.f);
}

// 16-input dot; weights and inputs both as 8 packed k-pairs held in registers.
__device__ __forceinline__ float dot16r(const u64 (&w)[8], const u64 (&v)[8],
                                        float bias) {
    u64 acc0 = pack2(bias, 0.f);
    u64 acc1 = pack2(0.f, 0.f);
#pragma unroll
    for (int p = 0; p < 4; p++) {
        acc0 = fma2(v[2 * p + 0], w[2 * p + 0], acc0);
        acc1 = fma2(v[2 * p + 1], w[2 * p + 1], acc1);
    }
    float2 s = unpack2(add2(acc0, acc1));
    return s.x + s.y;
}

__global__ void __launch_bounds__(NTHR) node_kernel(
    const float* __restrict__ times, const float* __restrict__ initial,
    const float* __restrict__ Wi,  const float* __restrict__ bi,
    const float* __restrict__ Wf0, const float* __restrict__ bf0,
    const float* __restrict__ Wf1, const float* __restrict__ bf1,
    const float* __restrict__ Wf2, const float* __restrict__ bf2,
    const float* __restrict__ Wf3, const float* __restrict__ bf3,
    const float* __restrict__ Wl,  const float* __restrict__ bl,
    float* __restrict__ out)
{
    // Transposed, zero-padded weight tiles (built once; the hot loop reads
    // NO shared memory except the sDt broadcast).
    __shared__ __align__(16) float sT1[16][16];   // Wf1^T  [j][k]
    __shared__ __align__(16) float sT2[16][16];   // Wf2^T  [j][k]
    __shared__ __align__(16) float sMt[16][16];   // M^T,   M = Wf3@Wf0   [15x15]
    __shared__ __align__(16) float sPt[8][16];    // P^T,   P = Wf3@Wl    [15x8]
    __shared__ __align__(16) float sWf0[32][16];  // Wf0    [c][j] padded
    __shared__ __align__(16) float sWi[INITD][HID];
    __shared__ __align__(16) float sWl[HID][OUTD];
    __shared__ float sB0[16], sB1[16], sB2[16], sC[16], sQ[OUTD], sBl[OUTD];
    __shared__ float sDt[TT - 1];

    const int tid = threadIdx.x;

    // ---- zero padded arrays ----
    for (int i = tid; i < 16 * 16; i += NTHR) {
        (&sT1[0][0])[i] = 0.f; (&sT2[0][0])[i] = 0.f; (&sMt[0][0])[i] = 0.f;
    }
    for (int i = tid; i < 8 * 16; i += NTHR)  (&sPt[0][0])[i]  = 0.f;
    for (int i = tid; i < 32 * 16; i += NTHR) (&sWf0[0][0])[i] = 0.f;
    if (tid < 16) { sB0[tid] = 0.f; sB1[tid] = 0.f; sB2[tid] = 0.f; sC[tid] = 0.f; }
    __syncthreads();

    // ---- fill transposed weights + fused operators ----
    for (int i = tid; i < HH * HH; i += NTHR) {       // Wf1/Wf2 [15][15]
        int k = i / HH, j = i % HH;
        sT1[j][k] = Wf1[i];
        sT2[j][k] = Wf2[i];
    }
    for (int i = tid; i < HID * HH; i += NTHR) {      // Wf0 [32][15]
        int c = i / HH, j = i % HH;
        sWf0[c][j] = Wf0[i];
    }
    for (int i = tid; i < INITD * HID; i += NTHR) (&sWi[0][0])[i] = Wi[i];
    for (int i = tid; i < HID * OUTD; i += NTHR)  (&sWl[0][0])[i] = Wl[i];

    // M = Wf3 @ Wf0 : M[k][j] = sum_m Wf3[k][m]*Wf0[m][j]   (stored transposed)
    for (int i = tid; i < HH * HH; i += NTHR) {
        int k = i / HH, j = i % HH;
        float acc = 0.f;
#pragma unroll
        for (int m = 0; m < HID; m++) acc = fmaf(Wf3[k * HID + m], Wf0[m * HH + j], acc);
        sMt[j][k] = acc;
    }
    // P = Wf3 @ Wl : P[k][o] = sum_m Wf3[k][m]*Wl[m][o]     (stored transposed)
    for (int i = tid; i < HH * OUTD; i += NTHR) {
        int k = i / OUTD, o = i % OUTD;
        float acc = 0.f;
#pragma unroll
        for (int m = 0; m < HID; m++) acc = fmaf(Wf3[k * HID + m], Wl[m * OUTD + o], acc);
        sPt[o][k] = acc;
    }
    // c = bf3 @ Wf0, q = bf3 @ Wl
    if (tid < HH) {
        float acc = 0.f;
#pragma unroll
        for (int m = 0; m < HID; m++) acc = fmaf(bf3[m], Wf0[m * HH + tid], acc);
        sC[tid] = acc;
    }
    if (tid < OUTD) {
        float acc = 0.f;
#pragma unroll
        for (int m = 0; m < HID; m++) acc = fmaf(bf3[m], Wl[m * OUTD + tid], acc);
        sQ[tid] = acc;
        sBl[tid] = bl[tid];
    }
    if (tid < HH) { sB0[tid] = bf0[tid]; sB1[tid] = bf1[tid]; sB2[tid] = bf2[tid]; }
    for (int t = tid; t < TT - 1; t += NTHR) sDt[t] = times[t + 1] - times[t];
    __syncthreads();

    // ---- mapping: 8 consecutive lanes = one batch element; role r in 0..7 ----
    const int e = blockIdx.x * EPB + (tid >> 3);
    const int r = tid & 7;
    const unsigned FULL = 0xffffffffu;

    // ---- hoist this role's weights into registers (packed k-pairs) ----
    u64 w1e[8], w1o[8], w2e[8], w2o[8], wMe[8], wMo[8], wP[8];
#pragma unroll
    for (int p = 0; p < 8; p++) {
        w1e[p] = *(const u64*)&sT1[2 * r][2 * p];
        w1o[p] = *(const u64*)&sT1[2 * r + 1][2 * p];
        w2e[p] = *(const u64*)&sT2[2 * r][2 * p];
        w2o[p] = *(const u64*)&sT2[2 * r + 1][2 * p];
        wMe[p] = *(const u64*)&sMt[2 * r][2 * p];
        wMo[p] = *(const u64*)&sMt[2 * r + 1][2 * p];
        wP[p]  = *(const u64*)&sPt[r][2 * p];
    }
    const float b1e = sB1[2 * r], b1o = sB1[2 * r + 1];
    const float b2e = sB2[2 * r], b2o = sB2[2 * r + 1];
    const float cE  = sC[2 * r],  cO  = sC[2 * r + 1];
    const float qr  = sQ[r];

    // ---- initial state: h0 = initial@Wi + bi (temporary), then
    //      u0 pair = (h0@Wf0 + bf0)[2r,2r+1],  y0 = (h0@Wl + bl)[r] ----
    u64 up;       // packed {u[2r], u[2r+1]}
    float yr;     // y[r]
    {
        float x[INITD];
#pragma unroll
        for (int k = 0; k < INITD; k++) x[k] = initial[e * INITD + k];
        float h0[HID];
#pragma unroll
        for (int c = 0; c < HID; c++) {
            float a = bi[c];
#pragma unroll
            for (int k = 0; k < INITD; k++) a = fmaf(x[k], sWi[k][c], a);
            h0[c] = a;
        }
        float ua = sB0[2 * r], ub = sB0[2 * r + 1];
        float y  = sBl[r];
#pragma unroll
        for (int c = 0; c < HID; c++) {
            ua = fmaf(h0[c], sWf0[c][2 * r],     ua);
            ub = fmaf(h0[c], sWf0[c][2 * r + 1], ub);
            y  = fmaf(h0[c], sWl[c][r],          y);
        }
        up = pack2(ua, ub);
        yr = y;
    }

    float* __restrict__ oute = out + (size_t)e * TT * OUTD;
    oute[r] = yr;

    u64 zp[8];
    for (int t = 0; t < TT - 1; t++) {
        const float dt = sDt[t];
        const u64 dt2 = pack2(dt, dt);

        // z0 = tanh(u)  (u pair is local; gather full z0)
        float2 uu = unpack2(up);
        u64 pl = pack2(ftanh(uu.x), ftanh(uu.y));
#pragma unroll
        for (int j = 0; j < 8; j++) zp[j] = __shfl_sync(FULL, pl, j, 8);

        // z1 = tanh(z0 @ Wf1 + b1)
        float a0 = ftanh(dot16r(w1e, zp, b1e));
        float a1 = ftanh(dot16r(w1o, zp, b1o));
        pl = pack2(a0, a1);
#pragma unroll
        for (int j = 0; j < 8; j++) zp[j] = __shfl_sync(FULL, pl, j, 8);

        // z2 = tanh(z1 @ Wf2 + b2)
        a0 = ftanh(dot16r(w2e, zp, b2e));
        a1 = ftanh(dot16r(w2o, zp, b2o));
        pl = pack2(a0, a1);
#pragma unroll
        for (int j = 0; j < 8; j++) zp[j] = __shfl_sync(FULL, pl, j, 8);

        // u += dt * (z2 @ M + c)   -- local pair only, no gather
        float d0 = dot16r(wMe, zp, cE);
        float d1 = dot16r(wMo, zp, cO);
        up = fma2(pack2(d0, d1), dt2, up);

        // y += dt * (z2 @ P + q)   -- local scalar, write out
        float dy = dot16r(wP, zp, qr);
        yr = fmaf(dt, dy, yr);
        oute[(size_t)(t + 1) * OUTD + r] = yr;
    }
}

extern "C" void kernel_launch(void* const* d_in, const int* in_sizes, int n_in,
                              void* d_out, int out_size) {
    const float* times   = (const float*)d_in[0];
    const float* initial = (const float*)d_in[1];
    const float* Wi  = (const float*)d_in[2];
    const float* bi  = (const float*)d_in[3];
    const float* Wf0 = (const float*)d_in[4];
    const float* bf0 = (const float*)d_in[5];
    const float* Wf1 = (const float*)d_in[6];
    const float* bf1 = (const float*)d_in[7];
    const float* Wf2 = (const float*)d_in[8];
    const float* bf2 = (const float*)d_in[9];
    const float* Wf3 = (const float*)d_in[10];
    const float* bf3 = (const float*)d_in[11];
    const float* Wl  = (const float*)d_in[12];
    const float* bl  = (const float*)d_in[13];
    float* out = (float*)d_out;

    node_kernel<<<NBLK, NTHR>>>(times, initial, Wi, bi,
                                Wf0, bf0, Wf1, bf1, Wf2, bf2, Wf3, bf3,
                                Wl, bl, out);
}